// round 3
// baseline (speedup 1.0000x reference)
#include <cuda_runtime.h>
#include <math.h>

#define BB 8
#define CC 64
#define NN 4096
#define KKN 32
#define EPS_BN 1e-5f
#define BN_TOTAL (BB*NN)   // 32768

// ---------------- scratch (static __device__, no allocs) ----------------
__device__ float g_feat[BB*NN*CC];   // (B*N, C) row-major
__device__ float g_sq  [BB*NN];
__device__ int   g_idx [BB*NN*KKN];
__device__ float g_Q   [BB*NN*CC];
__device__ float g_Pk  [BB*NN*CC];
__device__ float g_Pv  [BB*NN*CC];
__device__ float g_s1  [BB*NN*CC];
__device__ float g_s2  [BB*NN*CC];
__device__ float g_part1[8192*128];
__device__ float g_part2[256*128];
__device__ float g_stats1[128];
__device__ float g_stats2[128];

// ---------------- K1: transpose x (B,C,N)->(B*N,C) + sq ----------------
__global__ void k_transpose(const float* __restrict__ x) {
  __shared__ float t[64*33];
  int b  = blockIdx.x >> 7;
  int n0 = (blockIdx.x & 127) << 5;
  int tid = threadIdx.x;
  for (int idx = tid; idx < 64*32; idx += 256) {
    int c = idx >> 5, nn = idx & 31;
    t[c*33+nn] = x[(b*CC + c)*NN + n0 + nn];
  }
  __syncthreads();
  for (int idx = tid; idx < 32*64; idx += 256) {
    int nn = idx >> 6, c = idx & 63;
    g_feat[(b*NN + n0 + nn)*CC + c] = t[c*33+nn];
  }
  if (tid < 32) {
    float s = 0.f;
    #pragma unroll
    for (int c = 0; c < 64; c++) { float v = t[c*33+tid]; s += v*v; }
    g_sq[b*NN + n0 + tid] = s;
  }
}

// ---------------- K2: fused distance GEMM + streaming top-32 ----------------
// block: 256 thr, 128 n-rows; loops 32 m-tiles of 128; per-row min-heap of 32.
#define KNN_SMEM_FLOATS (64*132*2 + 128*129 + 128*33*2 + 256)
__global__ void __launch_bounds__(256) k_knn() {
  extern __shared__ float sm[];
  float* As   = sm;                    // [64][132]  feat[n][k] transposed
  float* Bs   = As + 64*132;           // [64][132]
  float* dist = Bs + 64*132;           // [128][129]
  float* hval = dist + 128*129;        // [128][33]
  int*   hidx = (int*)(hval + 128*33); // [128][33]
  float* sqn  = (float*)(hidx + 128*33);
  float* sqm  = sqn + 128;

  int b  = blockIdx.x >> 5;
  int n0 = (blockIdx.x & 31) << 7;
  int tid = threadIdx.x;
  int tx = tid & 15, ty = tid >> 4;

  for (int idx = tid; idx < 128*64; idx += 256) {
    int r = idx >> 6, k = idx & 63;
    As[k*132 + r] = g_feat[(b*NN + n0 + r)*CC + k];
  }
  if (tid < 128) {
    sqn[tid] = g_sq[b*NN + n0 + tid];
    #pragma unroll
    for (int i = 0; i < 32; i++) { hval[tid*33+i] = -3.4e38f; hidx[tid*33+i] = 0; }
  }
  __syncthreads();

  for (int mt = 0; mt < 32; mt++) {
    int m0 = mt << 7;
    for (int idx = tid; idx < 128*64; idx += 256) {
      int r = idx >> 6, k = idx & 63;
      Bs[k*132 + r] = g_feat[(b*NN + m0 + r)*CC + k];
    }
    if (tid < 128) sqm[tid] = g_sq[b*NN + m0 + tid];
    __syncthreads();

    float acc[8][8];
    #pragma unroll
    for (int i = 0; i < 8; i++)
      #pragma unroll
      for (int j = 0; j < 8; j++) acc[i][j] = 0.f;

    #pragma unroll 8
    for (int kk = 0; kk < 64; kk++) {
      float4 a0 = *(const float4*)&As[kk*132 + ty*8];
      float4 a1 = *(const float4*)&As[kk*132 + ty*8 + 4];
      float4 b0 = *(const float4*)&Bs[kk*132 + tx*8];
      float4 b1 = *(const float4*)&Bs[kk*132 + tx*8 + 4];
      float av[8] = {a0.x,a0.y,a0.z,a0.w,a1.x,a1.y,a1.z,a1.w};
      float bv[8] = {b0.x,b0.y,b0.z,b0.w,b1.x,b1.y,b1.z,b1.w};
      #pragma unroll
      for (int i = 0; i < 8; i++)
        #pragma unroll
        for (int j = 0; j < 8; j++) acc[i][j] += av[i]*bv[j];
    }

    #pragma unroll
    for (int i = 0; i < 8; i++) {
      int r = ty*8+i; float sr = sqn[r];
      #pragma unroll
      for (int j = 0; j < 8; j++) {
        int c = tx*8+j;
        dist[r*129+c] = 2.0f*acc[i][j] - sr - sqm[c];
      }
    }
    __syncthreads();

    if (tid < 128) {
      int r = tid;
      float* hv = &hval[r*33];
      int*   hi = &hidx[r*33];
      float hmin = hv[0];
      for (int j = 0; j < 128; j++) {
        float v = dist[r*129+j];
        if (v > hmin) {                 // strict >: earlier index wins ties
          int m = m0 + j;
          int pos = 0;
          for (;;) {
            int l = 2*pos+1;
            if (l >= 32) break;
            float cv = hv[l]; int cpos = l;
            int rr = l+1;
            if (rr < 32) { float rv2 = hv[rr]; if (rv2 < cv) { cv = rv2; cpos = rr; } }
            if (cv >= v) break;
            hv[pos] = cv; hi[pos] = hi[cpos];
            pos = cpos;
          }
          hv[pos] = v; hi[pos] = m;
          hmin = hv[0];
        }
      }
    }
    __syncthreads();
  }

  if (tid < 128) {
    int r = tid;
    #pragma unroll
    for (int i = 0; i < 32; i++)
      g_idx[(b*NN + n0 + r)*KKN + i] = hidx[r*33+i];
  }
}

// ---------------- K3: Q/Pk/Pv projections (feat @ W^T) ----------------
#define QKV_SMEM_FLOATS (3*64*65 + 64*65)
__global__ void __launch_bounds__(256) k_qkv(const float* __restrict__ wq,
                                             const float* __restrict__ wk,
                                             const float* __restrict__ wv) {
  extern __shared__ float sm[];
  float* ws = sm;              // [3][64][65]
  float* ft = ws + 3*64*65;    // [64][65]
  int tid = threadIdx.x;
  int row0 = blockIdx.x << 6;
  for (int idx = tid; idx < 64*64; idx += 256) {
    int o = idx >> 6, c = idx & 63;
    ws[0*4160 + o*65 + c] = wq[idx];
    ws[1*4160 + o*65 + c] = wk[idx];
    ws[2*4160 + o*65 + c] = wv[idx];
    ft[o*65 + c] = g_feat[(row0 + o)*CC + c];
  }
  __syncthreads();
  for (int t = tid; t < 64*192; t += 256) {
    int r  = t / 192;
    int o3 = t - r*192;
    int w = o3 >> 6, o = o3 & 63;
    const float* wr = &ws[w*4160 + o*65];
    const float* fr = &ft[r*65];
    float s = 0.f;
    #pragma unroll
    for (int c = 0; c < 64; c++) s += fr[c]*wr[c];
    float* dst = (w == 0) ? g_Q : (w == 1) ? g_Pk : g_Pv;
    dst[(row0+r)*CC + o] = s;
  }
}

// ---------------- K4: attention via gathered projections + BN1 partials ----------------
__global__ void __launch_bounds__(256) k_attn() {
  __shared__ float rsum[4][64], rsq[4][64];
  int tx = threadIdx.x, ty = threadIdx.y;
  int bn = blockIdx.x*4 + ty;
  int c = tx;
  int b = bn >> 12;
  float q   = g_Q [bn*64+c];
  float pkn = g_Pk[bn*64+c];
  float pvn = g_Pv[bn*64+c];
  float ft  = g_feat[bn*64+c];
  const int* ids = &g_idx[bn*KKN];
  int base_b = b*NN;
  float e[32], vd[32];
  #pragma unroll
  for (int k = 0; k < 32; k++) {
    int j = ids[k];
    int base = (base_b + j)*64 + c;
    float pk = g_Pk[base], pv = g_Pv[base];
    vd[k] = pv - pvn;
    float p = q * (pk - pkn);
    p += __shfl_xor_sync(0xffffffffu, p, 8);
    p += __shfl_xor_sync(0xffffffffu, p, 4);
    p += __shfl_xor_sync(0xffffffffu, p, 2);
    p += __shfl_xor_sync(0xffffffffu, p, 1);
    e[k] = p * 0.25f;   // /sqrt(D=16)
  }
  float mx = -3.4e38f;
  #pragma unroll
  for (int k = 0; k < 32; k++) mx = fmaxf(mx, e[k]);
  float s = 0.f;
  #pragma unroll
  for (int k = 0; k < 32; k++) { float ex = __expf(e[k]-mx); e[k] = ex; s += ex; }
  float inv = 1.0f/s;
  float out = 0.f;
  #pragma unroll
  for (int k = 0; k < 32; k++) out += e[k]*vd[k];
  out *= inv;
  float s1 = ft + out;
  g_s1[bn*64+c] = s1;
  rsum[ty][c] = s1; rsq[ty][c] = s1*s1;
  __syncthreads();
  if (ty == 0) {
    float a  = rsum[0][c]+rsum[1][c]+rsum[2][c]+rsum[3][c];
    float b2 = rsq [0][c]+rsq [1][c]+rsq [2][c]+rsq [3][c];
    g_part1[blockIdx.x*128 + c]      = a;
    g_part1[blockIdx.x*128 + 64 + c] = b2;
  }
}

// ---------------- deterministic stat reductions ----------------
__device__ __forceinline__ void reduce_body(const float* __restrict__ part, int nblocks, float* __restrict__ stats) {
  __shared__ float red[256];
  int s = blockIdx.x;
  float acc = 0.f;
  for (int i = threadIdx.x; i < nblocks; i += 256) acc += part[i*128 + s];
  red[threadIdx.x] = acc;
  __syncthreads();
  for (int off = 128; off > 0; off >>= 1) {
    if (threadIdx.x < off) red[threadIdx.x] += red[threadIdx.x+off];
    __syncthreads();
  }
  if (threadIdx.x == 0) stats[s] = red[0];
}
__global__ void k_reduce1() { reduce_body(g_part1, 8192, g_stats1); }
__global__ void k_reduce2() { reduce_body(g_part2, 256,  g_stats2); }

// ---------------- K5: BN1 apply + MLP + residual + BN2 partials ----------------
#define MLP_SMEM_FLOATS (256*65 + 64*257 + 64 + 256 + 256 + 64 + 64 + 64 + 64)
__global__ void __launch_bounds__(256) k_mlp(const float* __restrict__ w1,
                                             const float* __restrict__ w2,
                                             const float* __restrict__ g1,
                                             const float* __restrict__ b1) {
  extern __shared__ float sm[];
  float* w1s  = sm;              // [256][65]
  float* w2s  = w1s + 256*65;    // [64][257]
  float* f1s  = w2s + 64*257;    // 64
  float* hids = f1s + 64;        // 256
  float* part = hids + 256;      // [4][64]
  float* sc1  = part + 256;      // 64
  float* bs1  = sc1 + 64;        // 64
  float* accs = bs1 + 64;        // 64
  float* accq = accs + 64;       // 64

  int tid = threadIdx.x;
  for (int idx = tid; idx < 256*64; idx += 256) {
    int o = idx >> 6, ci = idx & 63;
    w1s[o*65+ci] = w1[idx];
  }
  for (int idx = tid; idx < 64*256; idx += 256) {
    int ci = idx >> 8, o = idx & 255;
    w2s[ci*257+o] = w2[idx];
  }
  if (tid < 64) {
    float sum = g_stats1[tid], sq = g_stats1[64+tid];
    float mu  = sum * (1.0f/BN_TOTAL);
    float var = sq  * (1.0f/BN_TOTAL) - mu*mu;
    float rs  = rsqrtf(var + EPS_BN);
    float scl = rs * g1[tid];
    sc1[tid] = scl;
    bs1[tid] = b1[tid] - mu*scl;
    accs[tid] = 0.f; accq[tid] = 0.f;
  }
  __syncthreads();

  int row0 = blockIdx.x << 7;   // 128 rows / block
  for (int r = 0; r < 128; r++) {
    int bn = row0 + r;
    if (tid < 64) f1s[tid] = g_s1[bn*64+tid]*sc1[tid] + bs1[tid];
    __syncthreads();
    {
      const float* wr = &w1s[tid*65];
      float s = 0.f;
      #pragma unroll
      for (int ci = 0; ci < 64; ci++) s += f1s[ci]*wr[ci];
      hids[tid] = (s > 0.f) ? s : 0.2f*s;   // LeakyReLU(0.2)
    }
    __syncthreads();
    {
      int ci = tid & 63, p = tid >> 6;
      const float* wr = &w2s[ci*257 + p*64];
      const float* hh = &hids[p*64];
      float s = 0.f;
      #pragma unroll
      for (int o = 0; o < 64; o++) s += hh[o]*wr[o];
      part[p*64 + ci] = s;
    }
    __syncthreads();
    if (tid < 64) {
      float ff = part[tid] + part[64+tid] + part[128+tid] + part[192+tid];
      float s2 = f1s[tid] + ff;
      g_s2[bn*64+tid] = s2;
      accs[tid] += s2; accq[tid] += s2*s2;
    }
    __syncthreads();
  }
  if (tid < 64) {
    g_part2[blockIdx.x*128 + tid]      = accs[tid];
    g_part2[blockIdx.x*128 + 64 + tid] = accq[tid];
  }
}

// ---------------- K6: BN2 apply + transpose to (B,C,N) ----------------
__global__ void k_out(float* __restrict__ out,
                      const float* __restrict__ g2,
                      const float* __restrict__ b2) {
  __shared__ float t[32*65];
  __shared__ float sc[64], bs[64];
  int tid = threadIdx.x;
  if (tid < 64) {
    float sum = g_stats2[tid], sq = g_stats2[64+tid];
    float mu  = sum * (1.0f/BN_TOTAL);
    float var = sq  * (1.0f/BN_TOTAL) - mu*mu;
    float rs  = rsqrtf(var + EPS_BN);
    float scl = rs*g2[tid];
    sc[tid] = scl; bs[tid] = b2[tid] - mu*scl;
  }
  __syncthreads();
  int b  = blockIdx.x >> 7;
  int n0 = (blockIdx.x & 127) << 5;
  for (int idx = tid; idx < 32*64; idx += 256) {
    int nn = idx >> 6, c = idx & 63;
    float v = g_s2[(b*NN + n0 + nn)*64 + c];
    t[nn*65 + c] = v*sc[c] + bs[c];
  }
  __syncthreads();
  for (int idx = tid; idx < 64*32; idx += 256) {
    int c = idx >> 5, nn = idx & 31;
    out[(b*CC + c)*NN + n0 + nn] = t[nn*65 + c];
  }
}

// ---------------- launch ----------------
extern "C" void kernel_launch(void* const* d_in, const int* in_sizes, int n_in,
                              void* d_out, int out_size) {
  (void)in_sizes; (void)n_in; (void)out_size;
  const float* x  = (const float*)d_in[0];
  const float* wq = (const float*)d_in[1];
  const float* wk = (const float*)d_in[2];
  const float* wv = (const float*)d_in[3];
  const float* w1 = (const float*)d_in[4];
  const float* w2 = (const float*)d_in[5];
  const float* g1 = (const float*)d_in[6];
  const float* b1 = (const float*)d_in[7];
  const float* g2 = (const float*)d_in[8];
  const float* b2 = (const float*)d_in[9];
  float* out = (float*)d_out;

  cudaFuncSetAttribute(k_knn, cudaFuncAttributeMaxDynamicSharedMemorySize, KNN_SMEM_FLOATS*4);
  cudaFuncSetAttribute(k_qkv, cudaFuncAttributeMaxDynamicSharedMemorySize, QKV_SMEM_FLOATS*4);
  cudaFuncSetAttribute(k_mlp, cudaFuncAttributeMaxDynamicSharedMemorySize, MLP_SMEM_FLOATS*4);

  k_transpose<<<1024, 256>>>(x);
  k_knn<<<256, 256, KNN_SMEM_FLOATS*4>>>();
  k_qkv<<<512, 256, QKV_SMEM_FLOATS*4>>>(wq, wk, wv);
  k_attn<<<8192, dim3(64,4)>>>();
  k_reduce1<<<128, 256>>>();
  k_mlp<<<256, 256, MLP_SMEM_FLOATS*4>>>(w1, w2, g1, b1);
  k_reduce2<<<128, 256>>>();
  k_out<<<1024, 256>>>(out, g2, b2);
}

// round 5
// speedup vs baseline: 1.1498x; 1.1498x over previous
#include <cuda_runtime.h>
#include <math.h>

#define BB 8
#define CC 64
#define NN 4096
#define KKN 32
#define EPS_BN 1e-5f
#define BN_TOTAL (BB*NN)   // 32768

// ---------------- scratch (static __device__, no allocs) ----------------
__device__ float g_feat[BB*NN*CC];   // (B*N, C) row-major
__device__ float g_sq  [BB*NN];
__device__ int   g_idx [BB*NN*KKN];
__device__ float g_Q   [BB*NN*CC];
__device__ float g_Pk  [BB*NN*CC];
__device__ float g_Pv  [BB*NN*CC];
__device__ float g_s1  [BB*NN*CC];
__device__ float g_s2  [BB*NN*CC];
__device__ float g_part1[8192*128];
__device__ float g_part2[256*128];
__device__ float g_stats1[128];
__device__ float g_stats2[128];

// ---------------- packed f32x2 helpers ----------------
__device__ __forceinline__ unsigned long long f2_fma(unsigned long long a,
                                                     unsigned long long b,
                                                     unsigned long long c) {
  unsigned long long d;
  asm("fma.rn.f32x2 %0, %1, %2, %3;" : "=l"(d) : "l"(a), "l"(b), "l"(c));
  return d;
}
__device__ __forceinline__ unsigned long long f2_dup(float x) {
  unsigned long long r;
  asm("mov.b64 %0, {%1, %1};" : "=l"(r) : "f"(x));
  return r;
}
__device__ __forceinline__ void f2_unpack(unsigned long long v, float& lo, float& hi) {
  asm("mov.b64 {%0, %1}, %2;" : "=f"(lo), "=f"(hi) : "l"(v));
}

// ---------------- K1: transpose x (B,C,N)->(B*N,C) + sq ----------------
__global__ void k_transpose(const float* __restrict__ x) {
  __shared__ float t[64*33];
  int b  = blockIdx.x >> 7;
  int n0 = (blockIdx.x & 127) << 5;
  int tid = threadIdx.x;
  for (int idx = tid; idx < 64*32; idx += 256) {
    int c = idx >> 5, nn = idx & 31;
    t[c*33+nn] = x[(b*CC + c)*NN + n0 + nn];
  }
  __syncthreads();
  for (int idx = tid; idx < 32*64; idx += 256) {
    int nn = idx >> 6, c = idx & 63;
    g_feat[(b*NN + n0 + nn)*CC + c] = t[c*33+nn];
  }
  if (tid < 32) {
    float s = 0.f;
    #pragma unroll
    for (int c = 0; c < 64; c++) { float v = t[c*33+tid]; s += v*v; }
    g_sq[b*NN + n0 + tid] = s;
  }
}

// ---------------- K2: fused distance GEMM (f32x2) + warp-ballot top-32 ----------------
// 512 threads, 128 n-rows/block, 32 m-tiles of 128.
#define KNN_SMEM_FLOATS (8448 + 8448 + 16896 + 4224 + 4224 + 128)
__device__ __forceinline__ void heap_insert(float* hv, int* hi, float v, int m) {
  int pos = 0;
  #pragma unroll 1
  for (;;) {
    int l = 2*pos + 1;
    if (l >= 32) break;
    float cv = hv[l]; int cp = l;
    int rr = l + 1;
    if (rr < 32) { float rv = hv[rr]; if (rv < cv) { cv = rv; cp = rr; } }
    if (cv >= v) break;
    hv[pos] = cv; hi[pos] = hi[cp];
    pos = cp;
  }
  hv[pos] = v; hi[pos] = m;
}

__global__ void __launch_bounds__(512) k_knn() {
  extern __shared__ float sm[];
  float* As   = sm;                     // [64][132] k-major, rows in inner dim
  float* Bs   = As + 8448;              // [64][132]
  float* dist = Bs + 8448;              // [128][132]
  float* hval = dist + 16896;           // [128][33]
  int*   hidx = (int*)(hval + 4224);    // [128][33]
  float* sqm  = (float*)(hidx + 4224);  // [128]

  int b  = blockIdx.x >> 5;
  int n0 = (blockIdx.x & 31) << 7;
  int tid  = threadIdx.x;
  int lane = tid & 31;
  int wid  = tid >> 5;                  // 0..15, warp = row group of 8

  for (int idx = tid; idx < 128*64; idx += 512) {
    int r = idx >> 6, k = idx & 63;
    As[k*132 + r] = g_feat[(b*NN + n0 + r)*CC + k];
  }
  if (tid < 128) {
    #pragma unroll
    for (int i = 0; i < 32; i++) { hval[tid*33+i] = -3.4e38f; hidx[tid*33+i] = 0; }
  }
  __syncthreads();

  #pragma unroll 1
  for (int mt = 0; mt < 32; mt++) {
    int m0 = mt << 7;
    for (int idx = tid; idx < 128*64; idx += 512) {
      int r = idx >> 6, k = idx & 63;
      Bs[k*132 + r] = g_feat[(b*NN + m0 + r)*CC + k];
    }
    if (tid < 128) sqm[tid] = g_sq[b*NN + m0 + tid];
    __syncthreads();

    // ---- GEMM: thread owns rows wid*8..+7 (4 packed pairs) x cols lane*4..+3 ----
    unsigned long long acc[4][4];
    unsigned long long zz = f2_dup(0.f);
    #pragma unroll
    for (int i = 0; i < 4; i++)
      #pragma unroll
      for (int j = 0; j < 4; j++) acc[i][j] = zz;

    const float* aBase = &As[wid*8];
    const float* bBase = &Bs[lane*4];
    #pragma unroll 4
    for (int kk = 0; kk < 64; kk++) {
      ulonglong2 ap0 = *(const ulonglong2*)(aBase + kk*132);      // rows {0,1},{2,3}
      ulonglong2 ap1 = *(const ulonglong2*)(aBase + kk*132 + 4);  // rows {4,5},{6,7}
      float4 bv = *(const float4*)(bBase + kk*132);
      unsigned long long b0 = f2_dup(bv.x), b1 = f2_dup(bv.y);
      unsigned long long b2 = f2_dup(bv.z), b3 = f2_dup(bv.w);
      acc[0][0] = f2_fma(ap0.x, b0, acc[0][0]);
      acc[0][1] = f2_fma(ap0.x, b1, acc[0][1]);
      acc[0][2] = f2_fma(ap0.x, b2, acc[0][2]);
      acc[0][3] = f2_fma(ap0.x, b3, acc[0][3]);
      acc[1][0] = f2_fma(ap0.y, b0, acc[1][0]);
      acc[1][1] = f2_fma(ap0.y, b1, acc[1][1]);
      acc[1][2] = f2_fma(ap0.y, b2, acc[1][2]);
      acc[1][3] = f2_fma(ap0.y, b3, acc[1][3]);
      acc[2][0] = f2_fma(ap1.x, b0, acc[2][0]);
      acc[2][1] = f2_fma(ap1.x, b1, acc[2][1]);
      acc[2][2] = f2_fma(ap1.x, b2, acc[2][2]);
      acc[2][3] = f2_fma(ap1.x, b3, acc[2][3]);
      acc[3][0] = f2_fma(ap1.y, b0, acc[3][0]);
      acc[3][1] = f2_fma(ap1.y, b1, acc[3][1]);
      acc[3][2] = f2_fma(ap1.y, b2, acc[3][2]);
      acc[3][3] = f2_fma(ap1.y, b3, acc[3][3]);
    }

    // epilogue: dist = 2*dot - sqm[c]  (per-row -sq[n] constant dropped: ordering invariant)
    {
      float4 sq4 = *(const float4*)&sqm[lane*4];
      #pragma unroll
      for (int p = 0; p < 4; p++) {       // row pair p -> rows 2p, 2p+1
        float v0[4], v1[4];
        #pragma unroll
        for (int j = 0; j < 4; j++) f2_unpack(acc[p][j], v0[j], v1[j]);
        float4 d0, d1;
        d0.x = 2.f*v0[0] - sq4.x; d0.y = 2.f*v0[1] - sq4.y;
        d0.z = 2.f*v0[2] - sq4.z; d0.w = 2.f*v0[3] - sq4.w;
        d1.x = 2.f*v1[0] - sq4.x; d1.y = 2.f*v1[1] - sq4.y;
        d1.z = 2.f*v1[2] - sq4.z; d1.w = 2.f*v1[3] - sq4.w;
        *(float4*)&dist[(wid*8 + 2*p    )*132 + lane*4] = d0;
        *(float4*)&dist[(wid*8 + 2*p + 1)*132 + lane*4] = d1;
      }
    }
    __syncthreads();

    // ---- selection: warp wid owns rows wid*8..+7; ballot scan, rare serial insert ----
    #pragma unroll 1
    for (int i = 0; i < 8; i++) {
      int r = wid*8 + i;
      float* hv = &hval[r*33];
      int*   hi = &hidx[r*33];
      float hmin = __shfl_sync(0xffffffffu, (lane == 0) ? hv[0] : 0.f, 0);
      #pragma unroll 1
      for (int cc = 0; cc < 4; cc++) {
        float v = dist[r*132 + cc*32 + lane];
        unsigned mask = __ballot_sync(0xffffffffu, v > hmin);
        #pragma unroll 1
        while (mask) {
          int src = __ffs(mask) - 1;
          mask &= mask - 1;
          float vv = __shfl_sync(0xffffffffu, v, src);
          if (vv > hmin) {
            if (lane == 0) heap_insert(hv, hi, vv, m0 + cc*32 + src);
            hmin = __shfl_sync(0xffffffffu, (lane == 0) ? hv[0] : 0.f, 0);
          }
        }
      }
    }
    __syncthreads();
  }

  for (int idx = tid; idx < 128*32; idx += 512) {
    int r = idx >> 5, i = idx & 31;
    g_idx[(b*NN + n0 + r)*KKN + i] = hidx[r*33 + i];
  }
}

// ---------------- K3: Q/Pk/Pv projections (feat @ W^T) ----------------
#define QKV_SMEM_FLOATS (3*64*65 + 64*65)
__global__ void __launch_bounds__(256) k_qkv(const float* __restrict__ wq,
                                             const float* __restrict__ wk,
                                             const float* __restrict__ wv) {
  extern __shared__ float sm[];
  float* ws = sm;              // [3][64][65]
  float* ft = ws + 3*64*65;    // [64][65]
  int tid = threadIdx.x;
  int row0 = blockIdx.x << 6;
  for (int idx = tid; idx < 64*64; idx += 256) {
    int o = idx >> 6, c = idx & 63;
    ws[0*4160 + o*65 + c] = wq[idx];
    ws[1*4160 + o*65 + c] = wk[idx];
    ws[2*4160 + o*65 + c] = wv[idx];
    ft[o*65 + c] = g_feat[(row0 + o)*CC + c];
  }
  __syncthreads();
  for (int t = tid; t < 64*192; t += 256) {
    int r  = t / 192;
    int o3 = t - r*192;
    int w = o3 >> 6, o = o3 & 63;
    const float* wr = &ws[w*4160 + o*65];
    const float* fr = &ft[r*65];
    float s = 0.f;
    #pragma unroll
    for (int c = 0; c < 64; c++) s += fr[c]*wr[c];
    float* dst = (w == 0) ? g_Q : (w == 1) ? g_Pk : g_Pv;
    dst[(row0+r)*CC + o] = s;
  }
}

// ---------------- K4: attention via gathered projections + BN1 partials ----------------
__global__ void __launch_bounds__(256) k_attn() {
  __shared__ float rsum[4][64], rsq[4][64];
  int tx = threadIdx.x, ty = threadIdx.y;
  int bn = blockIdx.x*4 + ty;
  int c = tx;
  int b = bn >> 12;
  float q   = g_Q [bn*64+c];
  float pkn = g_Pk[bn*64+c];
  float pvn = g_Pv[bn*64+c];
  float ft  = g_feat[bn*64+c];
  const int* ids = &g_idx[bn*KKN];
  int base_b = b*NN;
  float e[32], vd[32];
  #pragma unroll
  for (int k = 0; k < 32; k++) {
    int j = ids[k];
    int base = (base_b + j)*64 + c;
    float pk = g_Pk[base], pv = g_Pv[base];
    vd[k] = pv - pvn;
    float p = q * (pk - pkn);
    p += __shfl_xor_sync(0xffffffffu, p, 8);
    p += __shfl_xor_sync(0xffffffffu, p, 4);
    p += __shfl_xor_sync(0xffffffffu, p, 2);
    p += __shfl_xor_sync(0xffffffffu, p, 1);
    e[k] = p * 0.25f;   // /sqrt(D=16)
  }
  float mx = -3.4e38f;
  #pragma unroll
  for (int k = 0; k < 32; k++) mx = fmaxf(mx, e[k]);
  float s = 0.f;
  #pragma unroll
  for (int k = 0; k < 32; k++) { float ex = __expf(e[k]-mx); e[k] = ex; s += ex; }
  float inv = 1.0f/s;
  float out = 0.f;
  #pragma unroll
  for (int k = 0; k < 32; k++) out += e[k]*vd[k];
  out *= inv;
  float s1 = ft + out;
  g_s1[bn*64+c] = s1;
  rsum[ty][c] = s1; rsq[ty][c] = s1*s1;
  __syncthreads();
  if (ty == 0) {
    float a  = rsum[0][c]+rsum[1][c]+rsum[2][c]+rsum[3][c];
    float b2 = rsq [0][c]+rsq [1][c]+rsq [2][c]+rsq [3][c];
    g_part1[blockIdx.x*128 + c]      = a;
    g_part1[blockIdx.x*128 + 64 + c] = b2;
  }
}

// ---------------- deterministic stat reductions ----------------
__device__ __forceinline__ void reduce_body(const float* __restrict__ part, int nblocks,
                                            float* __restrict__ stats) {
  __shared__ float red[256];
  int s = blockIdx.x;
  float acc = 0.f;
  for (int i = threadIdx.x; i < nblocks; i += 256) acc += part[i*128 + s];
  red[threadIdx.x] = acc;
  __syncthreads();
  for (int off = 128; off > 0; off >>= 1) {
    if (threadIdx.x < off) red[threadIdx.x] += red[threadIdx.x+off];
    __syncthreads();
  }
  if (threadIdx.x == 0) stats[s] = red[0];
}
__global__ void k_reduce1() { reduce_body(g_part1, 8192, g_stats1); }
__global__ void k_reduce2() { reduce_body(g_part2, 256,  g_stats2); }

// ---------------- K5: BN1 apply + MLP + residual + BN2 partials ----------------
// 512 threads, 8 rows per iteration, 16 iterations (128 rows/block), 256 blocks.
#define MLP_SMEM_FLOATS (256*65 + 64*257 + 512 + 2048 + 64 + 64)
__global__ void __launch_bounds__(512) k_mlp(const float* __restrict__ w1,
                                             const float* __restrict__ w2,
                                             const float* __restrict__ g1,
                                             const float* __restrict__ b1) {
  extern __shared__ float sm[];
  float* w1s  = sm;               // [256][65]
  float* w2s  = w1s + 256*65;     // [64][257]
  float* f1s  = w2s + 64*257;     // [8][64]
  float* hids = f1s + 512;        // [8][256]
  float* sc1  = hids + 2048;      // 64
  float* bs1  = sc1 + 64;         // 64

  int tid = threadIdx.x;
  for (int idx = tid; idx < 256*64; idx += 512) {
    int o = idx >> 6, ci = idx & 63;
    w1s[o*65+ci] = w1[idx];
  }
  for (int idx = tid; idx < 64*256; idx += 512) {
    int ci = idx >> 8, o = idx & 255;
    w2s[ci*257+o] = w2[idx];
  }
  if (tid < 64) {
    float sum = g_stats1[tid], sq = g_stats1[64+tid];
    float mu  = sum * (1.0f/BN_TOTAL);
    float var = sq  * (1.0f/BN_TOTAL) - mu*mu;
    float rs  = rsqrtf(var + EPS_BN);
    float scl = rs * g1[tid];
    sc1[tid] = scl;
    bs1[tid] = b1[tid] - mu*scl;
  }
  __syncthreads();

  int row0 = blockIdx.x << 7;        // 128 rows / block
  int myc = tid & 63;                // channel for out phase
  int myrow = tid >> 6;              // row-in-group for out phase
  float accs_r = 0.f, accq_r = 0.f;
  float mysc = sc1[myc], mybs = bs1[myc];

  #pragma unroll 1
  for (int it = 0; it < 16; it++) {
    int bn0 = row0 + it*8;
    f1s[tid] = g_s1[(bn0 + myrow)*64 + myc] * mysc + mybs;
    __syncthreads();
    #pragma unroll
    for (int u = 0; u < 4; u++) {
      int item = tid + u*512;
      int rr = item >> 8, o = item & 255;
      const float* wr = &w1s[o*65];
      const float* fr = &f1s[rr*64];
      float s = 0.f;
      #pragma unroll
      for (int ci = 0; ci < 64; ci++) s += fr[ci]*wr[ci];
      hids[item] = (s > 0.f) ? s : 0.2f*s;   // LeakyReLU(0.2)
    }
    __syncthreads();
    {
      const float* wr = &w2s[myc*257];
      const float* hh = &hids[myrow*256];
      float s = 0.f;
      #pragma unroll
      for (int o = 0; o < 256; o++) s += hh[o]*wr[o];
      float s2 = f1s[tid] + s;
      g_s2[(bn0 + myrow)*64 + myc] = s2;
      accs_r += s2; accq_r += s2*s2;
    }
    __syncthreads();
  }
  hids[tid] = accs_r; hids[512 + tid] = accq_r;
  __syncthreads();
  if (tid < 64) {
    float a = 0.f, b2 = 0.f;
    #pragma unroll
    for (int rr = 0; rr < 8; rr++) { a += hids[rr*64 + tid]; b2 += hids[512 + rr*64 + tid]; }
    g_part2[blockIdx.x*128 + tid]      = a;
    g_part2[blockIdx.x*128 + 64 + tid] = b2;
  }
}

// ---------------- K6: BN2 apply + transpose to (B,C,N) ----------------
__global__ void k_out(float* __restrict__ out,
                      const float* __restrict__ g2,
                      const float* __restrict__ b2) {
  __shared__ float t[32*65];
  __shared__ float sc[64], bs[64];
  int tid = threadIdx.x;
  if (tid < 64) {
    float sum = g_stats2[tid], sq = g_stats2[64+tid];
    float mu  = sum * (1.0f/BN_TOTAL);
    float var = sq  * (1.0f/BN_TOTAL) - mu*mu;
    float rs  = rsqrtf(var + EPS_BN);
    float scl = rs*g2[tid];
    sc[tid] = scl; bs[tid] = b2[tid] - mu*scl;
  }
  __syncthreads();
  int b  = blockIdx.x >> 7;
  int n0 = (blockIdx.x & 127) << 5;
  for (int idx = tid; idx < 32*64; idx += 256) {
    int nn = idx >> 6, c = idx & 63;
    float v = g_s2[(b*NN + n0 + nn)*64 + c];
    t[nn*65 + c] = v*sc[c] + bs[c];
  }
  __syncthreads();
  for (int idx = tid; idx < 64*32; idx += 256) {
    int c = idx >> 5, nn = idx & 31;
    out[(b*CC + c)*NN + n0 + nn] = t[nn*65 + c];
  }
}

// ---------------- launch ----------------
extern "C" void kernel_launch(void* const* d_in, const int* in_sizes, int n_in,
                              void* d_out, int out_size) {
  (void)in_sizes; (void)n_in; (void)out_size;
  const float* x  = (const float*)d_in[0];
  const float* wq = (const float*)d_in[1];
  const float* wk = (const float*)d_in[2];
  const float* wv = (const float*)d_in[3];
  const float* w1 = (const float*)d_in[4];
  const float* w2 = (const float*)d_in[5];
  const float* g1 = (const float*)d_in[6];
  const float* b1 = (const float*)d_in[7];
  const float* g2 = (const float*)d_in[8];
  const float* b2 = (const float*)d_in[9];
  float* out = (float*)d_out;

  cudaFuncSetAttribute(k_knn, cudaFuncAttributeMaxDynamicSharedMemorySize, KNN_SMEM_FLOATS*4);
  cudaFuncSetAttribute(k_qkv, cudaFuncAttributeMaxDynamicSharedMemorySize, QKV_SMEM_FLOATS*4);
  cudaFuncSetAttribute(k_mlp, cudaFuncAttributeMaxDynamicSharedMemorySize, MLP_SMEM_FLOATS*4);

  k_transpose<<<1024, 256>>>(x);
  k_knn<<<256, 512, KNN_SMEM_FLOATS*4>>>();
  k_qkv<<<512, 256, QKV_SMEM_FLOATS*4>>>(wq, wk, wv);
  k_attn<<<8192, dim3(64,4)>>>();
  k_reduce1<<<128, 256>>>();
  k_mlp<<<256, 512, MLP_SMEM_FLOATS*4>>>(w1, w2, g1, b1);
  k_reduce2<<<128, 256>>>();
  k_out<<<1024, 256>>>(out, g2, b2);
}

// round 8
// speedup vs baseline: 2.3425x; 2.0373x over previous
#include <cuda_runtime.h>
#include <math.h>

#define BB 8
#define CC 64
#define NN 4096
#define KKN 32
#define EPS_BN 1e-5f
#define BN_TOTAL (BB*NN)   // 32768

// ---------------- scratch (static __device__, no allocs) ----------------
__device__ float g_feat[BB*NN*CC];   // (B*N, C) row-major
__device__ float g_sq  [BB*NN];
__device__ int   g_idx [BB*NN*KKN];
__device__ float g_dist[2u*NN*NN];   // 128MB: distance rows for 2 batches per pass
__device__ float g_Q   [BB*NN*CC];
__device__ float g_Pk  [BB*NN*CC];
__device__ float g_Pv  [BB*NN*CC];
__device__ float g_s1  [BB*NN*CC];
__device__ float g_s2  [BB*NN*CC];
__device__ float g_part1[8192*128];
__device__ float g_part2[256*128];
__device__ float g_stats1[128];
__device__ float g_stats2[128];

// ---------------- packed f32x2 helpers ----------------
__device__ __forceinline__ unsigned long long f2_fma(unsigned long long a,
                                                     unsigned long long b,
                                                     unsigned long long c) {
  unsigned long long d;
  asm("fma.rn.f32x2 %0, %1, %2, %3;" : "=l"(d) : "l"(a), "l"(b), "l"(c));
  return d;
}
__device__ __forceinline__ unsigned long long f2_dup(float x) {
  unsigned long long r;
  asm("mov.b64 %0, {%1, %1};" : "=l"(r) : "f"(x));
  return r;
}
__device__ __forceinline__ void f2_unpack(unsigned long long v, float& lo, float& hi) {
  asm("mov.b64 {%0, %1}, %2;" : "=f"(lo), "=f"(hi) : "l"(v));
}

// ---------------- K1: transpose x (B,C,N)->(B*N,C) + sq ----------------
__global__ void k_transpose(const float* __restrict__ x) {
  __shared__ float t[64*33];
  int b  = blockIdx.x >> 7;
  int n0 = (blockIdx.x & 127) << 5;
  int tid = threadIdx.x;
  for (int idx = tid; idx < 64*32; idx += 256) {
    int c = idx >> 5, nn = idx & 31;
    t[c*33+nn] = x[(b*CC + c)*NN + n0 + nn];
  }
  __syncthreads();
  for (int idx = tid; idx < 32*64; idx += 256) {
    int nn = idx >> 6, c = idx & 63;
    g_feat[(b*NN + n0 + nn)*CC + c] = t[c*33+nn];
  }
  if (tid < 32) {
    float s = 0.f;
    #pragma unroll
    for (int c = 0; c < 64; c++) { float v = t[c*33+tid]; s += v*v; }
    g_sq[b*NN + n0 + tid] = s;
  }
}

// ---------------- K2a: gram/distance GEMM, materialized ----------------
// grid (32, 32, 2): i-tile, j-tile, batch-in-pass. 256 threads, 128x128 tile, K=64.
// D[n][m] = 2*dot(f_n, f_m) - sq[m]   (row-constant -sq[n] dropped: ordering-invariant)
#define GRAM_SMEM_FLOATS (8448 + 8448 + 128)
__global__ void __launch_bounds__(256) k_gram(int pass) {
  extern __shared__ float sm[];
  float* As  = sm;            // [64][132]  As[k][r] = feat[i*128+r][k]
  float* Bs  = As + 8448;     // [64][132]
  float* sqm = Bs + 8448;     // [128]

  int it = blockIdx.x, jt = blockIdx.y, bz = blockIdx.z;
  int b = pass*2 + bz;
  int tid = threadIdx.x;
  int tx = tid & 15, ty = tid >> 4;

  const float* fA = g_feat + ((size_t)(b*NN + it*128))*CC;
  const float* fB = g_feat + ((size_t)(b*NN + jt*128))*CC;
  for (int idx = tid; idx < 8192; idx += 256) {
    int r = idx >> 6, k = idx & 63;
    As[k*132 + r] = fA[r*CC + k];
    Bs[k*132 + r] = fB[r*CC + k];
  }
  if (tid < 128) sqm[tid] = g_sq[b*NN + jt*128 + tid];
  __syncthreads();

  unsigned long long acc[4][8];
  unsigned long long zz = f2_dup(0.f);
  #pragma unroll
  for (int p = 0; p < 4; p++)
    #pragma unroll
    for (int q = 0; q < 8; q++) acc[p][q] = zz;

  const float* aB = &As[ty*8];
  const float* bB = &Bs[tx*8];
  #pragma unroll 8
  for (int kk = 0; kk < 64; kk++) {
    ulonglong2 a0 = *(const ulonglong2*)(aB + kk*132);      // row pairs {0,1},{2,3}
    ulonglong2 a1 = *(const ulonglong2*)(aB + kk*132 + 4);  // {4,5},{6,7}
    float4 b0 = *(const float4*)(bB + kk*132);
    float4 b1 = *(const float4*)(bB + kk*132 + 4);
    unsigned long long bb[8];
    bb[0] = f2_dup(b0.x); bb[1] = f2_dup(b0.y); bb[2] = f2_dup(b0.z); bb[3] = f2_dup(b0.w);
    bb[4] = f2_dup(b1.x); bb[5] = f2_dup(b1.y); bb[6] = f2_dup(b1.z); bb[7] = f2_dup(b1.w);
    #pragma unroll
    for (int q = 0; q < 8; q++) {
      acc[0][q] = f2_fma(a0.x, bb[q], acc[0][q]);
      acc[1][q] = f2_fma(a0.y, bb[q], acc[1][q]);
      acc[2][q] = f2_fma(a1.x, bb[q], acc[2][q]);
      acc[3][q] = f2_fma(a1.y, bb[q], acc[3][q]);
    }
  }

  // epilogue
  float4 sq0 = *(const float4*)&sqm[tx*8];
  float4 sq1 = *(const float4*)&sqm[tx*8 + 4];
  size_t dbase = (size_t)bz*NN*NN;
  #pragma unroll
  for (int p = 0; p < 4; p++) {
    float lo[8], hi[8];
    #pragma unroll
    for (int q = 0; q < 8; q++) f2_unpack(acc[p][q], lo[q], hi[q]);
    float4 r0a = { 2.f*lo[0]-sq0.x, 2.f*lo[1]-sq0.y, 2.f*lo[2]-sq0.z, 2.f*lo[3]-sq0.w };
    float4 r0b = { 2.f*lo[4]-sq1.x, 2.f*lo[5]-sq1.y, 2.f*lo[6]-sq1.z, 2.f*lo[7]-sq1.w };
    float4 r1a = { 2.f*hi[0]-sq0.x, 2.f*hi[1]-sq0.y, 2.f*hi[2]-sq0.z, 2.f*hi[3]-sq0.w };
    float4 r1b = { 2.f*hi[4]-sq1.x, 2.f*hi[5]-sq1.y, 2.f*hi[6]-sq1.z, 2.f*hi[7]-sq1.w };
    size_t row0 = (size_t)(it*128 + ty*8 + 2*p);
    float* d0 = g_dist + dbase + row0*NN + jt*128 + tx*8;
    float* d1 = d0 + NN;
    *(float4*)d0 = r0a; *(float4*)(d0+4) = r0b;
    *(float4*)d1 = r1a; *(float4*)(d1+4) = r1b;
  }
}

// ---------------- K2b: warp-per-row streaming top-32 ----------------
// 256 thr = 8 warps/block; 1024 blocks per pass (8192 rows).
// Top-32 kept as a sorted (desc) register list across lanes; lane 31 = current min.
__global__ void __launch_bounds__(256) k_select(int pass) {
  const unsigned FULL = 0xffffffffu;
  int warp = threadIdx.x >> 5, lane = threadIdx.x & 31;
  int row_local = blockIdx.x*8 + warp;            // 0..8191
  const float4* Drow = (const float4*)(g_dist + (size_t)row_local*NN);
  int b = pass*2 + (row_local >> 12);
  int n = row_local & (NN-1);

  float tv = -3.4e38f; int ti = 0;
  float hmin = -3.4e38f;

  #pragma unroll 1
  for (int c = 0; c < 32; c++) {
    float4 v4 = Drow[c*32 + lane];
    float vj[4] = {v4.x, v4.y, v4.z, v4.w};
    #pragma unroll
    for (int jj = 0; jj < 4; jj++) {
      unsigned mask = __ballot_sync(FULL, vj[jj] > hmin);
      #pragma unroll 1
      while (mask) {
        int src = __ffs(mask) - 1;
        mask &= mask - 1;
        float vv = __shfl_sync(FULL, vj[jj], src);
        if (vv > hmin) {
          int idx = c*128 + src*4 + jj;
          unsigned ge = __ballot_sync(FULL, tv >= vv);  // prefix (sorted desc)
          int pos = __popc(ge);                          // insert after equals
          float su = __shfl_up_sync(FULL, tv, 1);
          int   si = __shfl_up_sync(FULL, ti, 1);
          if (lane > pos)       { tv = su; ti = si; }
          else if (lane == pos) { tv = vv; ti = idx; }
          hmin = __shfl_sync(FULL, tv, 31);
        }
      }
    }
  }
  g_idx[((size_t)(b*NN + n))*KKN + lane] = ti;
}

// ---------------- K3: Q/Pk/Pv projections (feat @ W^T) ----------------
#define QKV_SMEM_FLOATS (3*64*65 + 64*65)
__global__ void __launch_bounds__(256) k_qkv(const float* __restrict__ wq,
                                             const float* __restrict__ wk,
                                             const float* __restrict__ wv) {
  extern __shared__ float sm[];
  float* ws = sm;              // [3][64][65]
  float* ft = ws + 3*64*65;    // [64][65]
  int tid = threadIdx.x;
  int row0 = blockIdx.x << 6;
  for (int idx = tid; idx < 64*64; idx += 256) {
    int o = idx >> 6, c = idx & 63;
    ws[0*4160 + o*65 + c] = wq[idx];
    ws[1*4160 + o*65 + c] = wk[idx];
    ws[2*4160 + o*65 + c] = wv[idx];
    ft[o*65 + c] = g_feat[(row0 + o)*CC + c];
  }
  __syncthreads();
  for (int t = tid; t < 64*192; t += 256) {
    int r  = t / 192;
    int o3 = t - r*192;
    int w = o3 >> 6, o = o3 & 63;
    const float* wr = &ws[w*4160 + o*65];
    const float* fr = &ft[r*65];
    float s = 0.f;
    #pragma unroll
    for (int c = 0; c < 64; c++) s += fr[c]*wr[c];
    float* dst = (w == 0) ? g_Q : (w == 1) ? g_Pk : g_Pv;
    dst[(row0+r)*CC + o] = s;
  }
}

// ---------------- K4: attention via gathered projections + BN1 partials ----------------
__global__ void __launch_bounds__(256) k_attn() {
  __shared__ float rsum[4][64], rsq[4][64];
  int tx = threadIdx.x, ty = threadIdx.y;
  int bn = blockIdx.x*4 + ty;
  int c = tx;
  int b = bn >> 12;
  float q   = g_Q [bn*64+c];
  float pkn = g_Pk[bn*64+c];
  float pvn = g_Pv[bn*64+c];
  float ft  = g_feat[bn*64+c];
  const int* ids = &g_idx[bn*KKN];
  int base_b = b*NN;
  float e[32], vd[32];
  #pragma unroll
  for (int k = 0; k < 32; k++) {
    int j = ids[k];
    int base = (base_b + j)*64 + c;
    float pk = g_Pk[base], pv = g_Pv[base];
    vd[k] = pv - pvn;
    float p = q * (pk - pkn);
    p += __shfl_xor_sync(0xffffffffu, p, 8);
    p += __shfl_xor_sync(0xffffffffu, p, 4);
    p += __shfl_xor_sync(0xffffffffu, p, 2);
    p += __shfl_xor_sync(0xffffffffu, p, 1);
    e[k] = p * 0.25f;   // /sqrt(D=16)
  }
  float mx = -3.4e38f;
  #pragma unroll
  for (int k = 0; k < 32; k++) mx = fmaxf(mx, e[k]);
  float s = 0.f;
  #pragma unroll
  for (int k = 0; k < 32; k++) { float ex = __expf(e[k]-mx); e[k] = ex; s += ex; }
  float inv = 1.0f/s;
  float out = 0.f;
  #pragma unroll
  for (int k = 0; k < 32; k++) out += e[k]*vd[k];
  out *= inv;
  float s1 = ft + out;
  g_s1[bn*64+c] = s1;
  rsum[ty][c] = s1; rsq[ty][c] = s1*s1;
  __syncthreads();
  if (ty == 0) {
    float a  = rsum[0][c]+rsum[1][c]+rsum[2][c]+rsum[3][c];
    float b2 = rsq [0][c]+rsq [1][c]+rsq [2][c]+rsq [3][c];
    g_part1[blockIdx.x*128 + c]      = a;
    g_part1[blockIdx.x*128 + 64 + c] = b2;
  }
}

// ---------------- deterministic stat reductions ----------------
__device__ __forceinline__ void reduce_body(const float* __restrict__ part, int nblocks,
                                            float* __restrict__ stats) {
  __shared__ float red[256];
  int s = blockIdx.x;
  float acc = 0.f;
  for (int i = threadIdx.x; i < nblocks; i += 256) acc += part[i*128 + s];
  red[threadIdx.x] = acc;
  __syncthreads();
  for (int off = 128; off > 0; off >>= 1) {
    if (threadIdx.x < off) red[threadIdx.x] += red[threadIdx.x+off];
    __syncthreads();
  }
  if (threadIdx.x == 0) stats[s] = red[0];
}
__global__ void k_reduce1() { reduce_body(g_part1, 8192, g_stats1); }
__global__ void k_reduce2() { reduce_body(g_part2, 256,  g_stats2); }

// ---------------- K5: BN1 apply + MLP + residual + BN2 partials ----------------
#define MLP_SMEM_FLOATS (256*65 + 64*257 + 512 + 2048 + 64 + 64)
__global__ void __launch_bounds__(512) k_mlp(const float* __restrict__ w1,
                                             const float* __restrict__ w2,
                                             const float* __restrict__ g1,
                                             const float* __restrict__ b1) {
  extern __shared__ float sm[];
  float* w1s  = sm;               // [256][65]
  float* w2s  = w1s + 256*65;     // [64][257]
  float* f1s  = w2s + 64*257;     // [8][64]
  float* hids = f1s + 512;        // [8][256]
  float* sc1  = hids + 2048;      // 64
  float* bs1  = sc1 + 64;         // 64

  int tid = threadIdx.x;
  for (int idx = tid; idx < 256*64; idx += 512) {
    int o = idx >> 6, ci = idx & 63;
    w1s[o*65+ci] = w1[idx];
  }
  for (int idx = tid; idx < 64*256; idx += 512) {
    int ci = idx >> 8, o = idx & 255;
    w2s[ci*257+o] = w2[idx];
  }
  if (tid < 64) {
    float sum = g_stats1[tid], sq = g_stats1[64+tid];
    float mu  = sum * (1.0f/BN_TOTAL);
    float var = sq  * (1.0f/BN_TOTAL) - mu*mu;
    float rs  = rsqrtf(var + EPS_BN);
    float scl = rs * g1[tid];
    sc1[tid] = scl;
    bs1[tid] = b1[tid] - mu*scl;
  }
  __syncthreads();

  int row0 = blockIdx.x << 7;        // 128 rows / block
  int myc = tid & 63;
  int myrow = tid >> 6;
  float accs_r = 0.f, accq_r = 0.f;
  float mysc = sc1[myc], mybs = bs1[myc];

  #pragma unroll 1
  for (int it = 0; it < 16; it++) {
    int bn0 = row0 + it*8;
    f1s[tid] = g_s1[(bn0 + myrow)*64 + myc] * mysc + mybs;
    __syncthreads();
    #pragma unroll
    for (int u = 0; u < 4; u++) {
      int item = tid + u*512;
      int rr = item >> 8, o = item & 255;
      const float* wr = &w1s[o*65];
      const float* fr = &f1s[rr*64];
      float s = 0.f;
      #pragma unroll
      for (int ci = 0; ci < 64; ci++) s += fr[ci]*wr[ci];
      hids[item] = (s > 0.f) ? s : 0.2f*s;   // LeakyReLU(0.2)
    }
    __syncthreads();
    {
      const float* wr = &w2s[myc*257];
      const float* hh = &hids[myrow*256];
      float s = 0.f;
      #pragma unroll
      for (int o = 0; o < 256; o++) s += hh[o]*wr[o];
      float s2 = f1s[tid] + s;
      g_s2[(bn0 + myrow)*64 + myc] = s2;
      accs_r += s2; accq_r += s2*s2;
    }
    __syncthreads();
  }
  hids[tid] = accs_r; hids[512 + tid] = accq_r;
  __syncthreads();
  if (tid < 64) {
    float a = 0.f, b2 = 0.f;
    #pragma unroll
    for (int rr = 0; rr < 8; rr++) { a += hids[rr*64 + tid]; b2 += hids[512 + rr*64 + tid]; }
    g_part2[blockIdx.x*128 + tid]      = a;
    g_part2[blockIdx.x*128 + 64 + tid] = b2;
  }
}

// ---------------- K6: BN2 apply + transpose to (B,C,N) ----------------
__global__ void k_out(float* __restrict__ out,
                      const float* __restrict__ g2,
                      const float* __restrict__ b2) {
  __shared__ float t[32*65];
  __shared__ float sc[64], bs[64];
  int tid = threadIdx.x;
  if (tid < 64) {
    float sum = g_stats2[tid], sq = g_stats2[64+tid];
    float mu  = sum * (1.0f/BN_TOTAL);
    float var = sq  * (1.0f/BN_TOTAL) - mu*mu;
    float rs  = rsqrtf(var + EPS_BN);
    float scl = rs*g2[tid];
    sc[tid] = scl; bs[tid] = b2[tid] - mu*scl;
  }
  __syncthreads();
  int b  = blockIdx.x >> 7;
  int n0 = (blockIdx.x & 127) << 5;
  for (int idx = tid; idx < 32*64; idx += 256) {
    int nn = idx >> 6, c = idx & 63;
    float v = g_s2[(b*NN + n0 + nn)*64 + c];
    t[nn*65 + c] = v*sc[c] + bs[c];
  }
  __syncthreads();
  for (int idx = tid; idx < 64*32; idx += 256) {
    int c = idx >> 5, nn = idx & 31;
    out[(b*CC + c)*NN + n0 + nn] = t[nn*65 + c];
  }
}

// ---------------- launch ----------------
extern "C" void kernel_launch(void* const* d_in, const int* in_sizes, int n_in,
                              void* d_out, int out_size) {
  (void)in_sizes; (void)n_in; (void)out_size;
  const float* x  = (const float*)d_in[0];
  const float* wq = (const float*)d_in[1];
  const float* wk = (const float*)d_in[2];
  const float* wv = (const float*)d_in[3];
  const float* w1 = (const float*)d_in[4];
  const float* w2 = (const float*)d_in[5];
  const float* g1 = (const float*)d_in[6];
  const float* b1 = (const float*)d_in[7];
  const float* g2 = (const float*)d_in[8];
  const float* b2 = (const float*)d_in[9];
  float* out = (float*)d_out;

  cudaFuncSetAttribute(k_gram, cudaFuncAttributeMaxDynamicSharedMemorySize, GRAM_SMEM_FLOATS*4);
  cudaFuncSetAttribute(k_qkv,  cudaFuncAttributeMaxDynamicSharedMemorySize, QKV_SMEM_FLOATS*4);
  cudaFuncSetAttribute(k_mlp,  cudaFuncAttributeMaxDynamicSharedMemorySize, MLP_SMEM_FLOATS*4);

  k_transpose<<<1024, 256>>>(x);
  k_qkv<<<512, 256, QKV_SMEM_FLOATS*4>>>(wq, wk, wv);
  for (int pass = 0; pass < 4; pass++) {
    k_gram<<<dim3(32, 32, 2), 256, GRAM_SMEM_FLOATS*4>>>(pass);
    k_select<<<1024, 256>>>(pass);
  }
  k_attn<<<8192, dim3(64,4)>>>();
  k_reduce1<<<128, 256>>>();
  k_mlp<<<256, 512, MLP_SMEM_FLOATS*4>>>(w1, w2, g1, b1);
  k_reduce2<<<128, 256>>>();
  k_out<<<1024, 256>>>(out, g2, b2);
}